// round 4
// baseline (speedup 1.0000x reference)
#include <cuda_runtime.h>
#include <cuda_fp16.h>
#include <cstdint>

#define Bc 2048
#define Tc 256
#define Ic 64
#define Hc 128
#define Gc 512
#define Mc (Bc * Tc)

// ---------------------------------------------------------------------------
// Scratch (device globals; no allocation allowed)
// ---------------------------------------------------------------------------
__device__ __half g_pre[(size_t)Mc * Gc];        // [B][T][4H] fp16 (row m = b*T+t)
__device__ __half g_seq0[(size_t)Mc * Hc];       // layer0 hidden [B][T][H] fp16
__device__ __half g_seq1[(size_t)Mc * Hc];       // layer1 hidden [B][T][H] fp16
__device__ float  g_scores[(size_t)Bc * Tc];     // attention logits [B][T]

// ---------------------------------------------------------------------------
// PTX helpers
// ---------------------------------------------------------------------------
__device__ __forceinline__ uint32_t su32(const void* p) {
    return (uint32_t)__cvta_generic_to_shared(p);
}
__device__ __forceinline__ void ldsm4(uint32_t a, uint32_t& r0, uint32_t& r1,
                                      uint32_t& r2, uint32_t& r3) {
    asm volatile("ldmatrix.sync.aligned.m8n8.x4.shared.b16 {%0,%1,%2,%3},[%4];"
                 : "=r"(r0), "=r"(r1), "=r"(r2), "=r"(r3) : "r"(a));
}
__device__ __forceinline__ void mma16816(float* d, const uint32_t* a, const uint32_t* b) {
    asm volatile(
        "mma.sync.aligned.m16n8k16.row.col.f32.f16.f16.f32 "
        "{%0,%1,%2,%3},{%4,%5,%6,%7},{%8,%9},{%0,%1,%2,%3};"
        : "+f"(d[0]), "+f"(d[1]), "+f"(d[2]), "+f"(d[3])
        : "r"(a[0]), "r"(a[1]), "r"(a[2]), "r"(a[3]), "r"(b[0]), "r"(b[1]));
}
__device__ __forceinline__ float tanh_f(float x) {
    float y; asm("tanh.approx.f32 %0,%1;" : "=f"(y) : "f"(x)); return y;
}
__device__ __forceinline__ uint32_t h2tanh(uint32_t x) {
    uint32_t y; asm("tanh.approx.f16x2 %0,%1;" : "=r"(y) : "r"(x)); return y;
}
// sigmoid(x) = 0.5*tanh(0.5x)+0.5, f16x2
__device__ __forceinline__ __half2 h2sig(__half2 x) {
    const __half2 hhalf = __floats2half2_rn(0.5f, 0.5f);
    __half2 t = __hmul2(x, hhalf);
    uint32_t tt = h2tanh(*(uint32_t*)&t);
    return __hfma2(*(__half2*)&tt, hhalf, hhalf);
}
__device__ __forceinline__ void cpa16(uint32_t d, const void* s) {
    asm volatile("cp.async.cg.shared.global [%0],[%1],16;" :: "r"(d), "l"(s));
}

// ---------------------------------------------------------------------------
// Pre-GEMM (HMMA): out[m][n] = A[m]·W[n] + b1[n] + b2[n], fp16 out, m-major.
// Block tile 128m x 128n. Epilogue staged through SMEM for coalesced stores.
// ---------------------------------------------------------------------------
template <int K, bool AHALF>
__global__ __launch_bounds__(256)
void gemm_pre_hmma(const void* __restrict__ Araw,
                   const float* __restrict__ W,
                   const float* __restrict__ b1f,
                   const float* __restrict__ b2f,
                   __half* __restrict__ out)
{
    constexpr int KP = K + 8;
    extern __shared__ char smraw[];
    __half* As = (__half*)smraw;            // [128][KP]
    __half* Bs = As + 128 * KP;             // [128][KP]
    float*  bsum = (float*)(Bs + 128 * KP); // [128]
    __half* Cs = As;                        // staging (reuses As/Bs region): [128][136]

    const int tid = threadIdx.x;
    const int m0 = blockIdx.x * 128, n0 = blockIdx.y * 128;

    if (AHALF) {
        const uint4* Ag = (const uint4*)((const __half*)Araw + (size_t)m0 * K);
        for (int i = tid; i < 128 * K / 8; i += 256) {
            int r = i / (K / 8), ch = i % (K / 8);
            *(uint4*)(As + r * KP + ch * 8) = Ag[i];
        }
    } else {
        const float4* Ag = (const float4*)((const float*)Araw + (size_t)m0 * K);
        for (int i = tid; i < 128 * K / 4; i += 256) {
            int r = i / (K / 4), ch = i % (K / 4);
            float4 v = Ag[i];
            *(__half2*)(As + r * KP + ch * 4)     = __floats2half2_rn(v.x, v.y);
            *(__half2*)(As + r * KP + ch * 4 + 2) = __floats2half2_rn(v.z, v.w);
        }
    }
    {
        const float4* Wg = (const float4*)(W + (size_t)n0 * K);
        for (int i = tid; i < 128 * K / 4; i += 256) {
            int r = i / (K / 4), ch = i % (K / 4);
            float4 v = Wg[i];
            *(__half2*)(Bs + r * KP + ch * 4)     = __floats2half2_rn(v.x, v.y);
            *(__half2*)(Bs + r * KP + ch * 4 + 2) = __floats2half2_rn(v.z, v.w);
        }
    }
    if (tid < 128) bsum[tid] = b1f[n0 + tid] + b2f[n0 + tid];
    __syncthreads();

    const int wid = tid >> 5, lane = tid & 31;
    const int wm = wid & 3, wn = wid >> 2;
    const int mat = lane >> 3, lr = lane & 7;

    float acc[2][8][4];
#pragma unroll
    for (int i = 0; i < 2; i++)
#pragma unroll
        for (int j = 0; j < 8; j++)
#pragma unroll
            for (int l = 0; l < 4; l++) acc[i][j][l] = 0.f;

#pragma unroll
    for (int kt = 0; kt < K / 16; kt++) {
        uint32_t a[2][4];
#pragma unroll
        for (int mt = 0; mt < 2; mt++) {
            int row = wm * 32 + mt * 16 + (mat & 1) * 8 + lr;
            int col = kt * 16 + (mat >> 1) * 8;
            ldsm4(su32(As + row * KP + col), a[mt][0], a[mt][1], a[mt][2], a[mt][3]);
        }
        uint32_t b[8][2];
#pragma unroll
        for (int nq = 0; nq < 4; nq++) {
            int nrow = wn * 64 + nq * 16 + (mat >> 1) * 8 + lr;
            int col  = kt * 16 + (mat & 1) * 8;
            uint32_t r0, r1, r2, r3;
            ldsm4(su32(Bs + nrow * KP + col), r0, r1, r2, r3);
            b[nq * 2][0] = r0; b[nq * 2][1] = r1;
            b[nq * 2 + 1][0] = r2; b[nq * 2 + 1][1] = r3;
        }
#pragma unroll
        for (int mt = 0; mt < 2; mt++)
#pragma unroll
            for (int nt = 0; nt < 8; nt++)
                mma16816(acc[mt][nt], a[mt], b[nt]);
    }

    __syncthreads();   // all ldmatrix reads done; safe to overwrite As/Bs

    // stage C (with bias) into SMEM [128][136]
#pragma unroll
    for (int mt = 0; mt < 2; mt++) {
#pragma unroll
        for (int nt = 0; nt < 8; nt++) {
            int lc = wn * 64 + nt * 8 + 2 * (lane & 3);
            float2 bs = *(float2*)&bsum[lc];
#pragma unroll
            for (int hh = 0; hh < 2; hh++) {
                int r = wm * 32 + mt * 16 + (lane >> 2) + hh * 8;
                *(__half2*)&Cs[r * 136 + lc] =
                    __floats2half2_rn(acc[mt][nt][hh * 2] + bs.x,
                                      acc[mt][nt][hh * 2 + 1] + bs.y);
            }
        }
    }
    __syncthreads();

    // coalesced store: each 16-thread group writes a full 256B row
    for (int i = tid; i < 128 * 16; i += 256) {
        int r = i >> 4, ch = i & 15;
        *(uint4*)&out[(size_t)(m0 + r) * Gc + n0 + ch * 8] =
            *(uint4*)&Cs[r * 136 + ch * 8];
    }
}

// ---------------------------------------------------------------------------
// LSTM recurrence (HMMA): block = 16 batch rows, 16 warps (512 threads).
// Warp w owns h-column group 8*w across all 4 gates (register-local cell).
// w_hh in registers as fp16 B-fragments; gate activations in f16x2.
// ---------------------------------------------------------------------------
__global__ __launch_bounds__(512, 1)
void lstm_rec_hmma(const __half* __restrict__ pre,    // [B][T][512]
                   const float*  __restrict__ w_hh,   // [512][128]
                   __half* __restrict__ seqout)       // [B][T][128]
{
    __shared__ __half h_sm[2][16][136];
    __shared__ __half pre_sm[2][16][520];

    const int tid = threadIdx.x, wid = tid >> 5, lane = tid & 31;
    const int b0 = blockIdx.x * 16;
    const int r_lo = lane >> 2;
    const int c_loc = 2 * (lane & 3);

    // Persistent B fragments: warp w owns gate cols n = 128*g + 8*w (+ lane n_off)
    uint32_t bf[8][4][2];
    {
#pragma unroll
        for (int g = 0; g < 4; g++) {
            int n = 128 * g + 8 * wid + r_lo;
            const float* wr = w_hh + (size_t)n * Hc + c_loc;
#pragma unroll
            for (int kt = 0; kt < 8; kt++) {
                float2 v0 = *(const float2*)(wr + kt * 16);
                float2 v1 = *(const float2*)(wr + kt * 16 + 8);
                __half2 h0 = __floats2half2_rn(v0.x, v0.y);
                __half2 h1 = __floats2half2_rn(v1.x, v1.y);
                bf[kt][g][0] = *(uint32_t*)&h0;
                bf[kt][g][1] = *(uint32_t*)&h1;
            }
        }
    }

    for (int i = tid; i < 2 * 16 * 136; i += 512)
        ((__half*)h_sm)[i] = __float2half(0.f);

    // prefetch pre(t=0): 16 rows x 1KB
#pragma unroll
    for (int j = 0; j < 2; j++) {
        int idx = tid + j * 512;
        int r = idx >> 6, ch = idx & 63;
        cpa16(su32(&pre_sm[0][r][ch * 8]),
              pre + ((size_t)(b0 + r) * Tc + 0) * Gc + ch * 8);
    }
    asm volatile("cp.async.commit_group;");

    float cst[4];
#pragma unroll
    for (int j = 0; j < 4; j++) cst[j] = 0.f;

    asm volatile("cp.async.wait_group 0;");
    __syncthreads();

    for (int t = 0; t < Tc; t++) {
        const int cur = t & 1, nxt = cur ^ 1;

        // acc init from pre tile (direct conflict-free half2 loads)
        float acc[4][4];
#pragma unroll
        for (int g = 0; g < 4; g++) {
            int cc = 128 * g + 8 * wid + c_loc;
            float2 lo = __half22float2(*(const __half2*)&pre_sm[cur][r_lo][cc]);
            float2 hi = __half22float2(*(const __half2*)&pre_sm[cur][r_lo + 8][cc]);
            acc[g][0] = lo.x; acc[g][1] = lo.y;
            acc[g][2] = hi.x; acc[g][3] = hi.y;
        }

        // prefetch pre(t+1) (hidden behind MMA)
        if (t + 1 < Tc) {
#pragma unroll
            for (int j = 0; j < 2; j++) {
                int idx = tid + j * 512;
                int r = idx >> 6, ch = idx & 63;
                cpa16(su32(&pre_sm[nxt][r][ch * 8]),
                      pre + ((size_t)(b0 + r) * Tc + (t + 1)) * Gc + ch * 8);
            }
        }
        asm volatile("cp.async.commit_group;");

        // gates += h(t-1) @ w_hh^T
#pragma unroll
        for (int kt = 0; kt < 8; kt++) {
            uint32_t a[4];
            a[0] = *(const uint32_t*)&h_sm[cur][r_lo    ][kt * 16 + c_loc];
            a[1] = *(const uint32_t*)&h_sm[cur][r_lo + 8][kt * 16 + c_loc];
            a[2] = *(const uint32_t*)&h_sm[cur][r_lo    ][kt * 16 + c_loc + 8];
            a[3] = *(const uint32_t*)&h_sm[cur][r_lo + 8][kt * 16 + c_loc + 8];
#pragma unroll
            for (int g = 0; g < 4; g++) mma16816(acc[g], a, bf[kt][g]);
        }

        // LSTM cell: gate activations in f16x2 (2 cols per op), c in fp32
#pragma unroll
        for (int jr = 0; jr < 2; jr++) {
            __half2 gi = __floats2half2_rn(acc[0][jr * 2], acc[0][jr * 2 + 1]);
            __half2 gf = __floats2half2_rn(acc[1][jr * 2], acc[1][jr * 2 + 1]);
            __half2 gz = __floats2half2_rn(acc[2][jr * 2], acc[2][jr * 2 + 1]);
            __half2 go = __floats2half2_rn(acc[3][jr * 2], acc[3][jr * 2 + 1]);
            float2 i_ = __half22float2(h2sig(gi));
            float2 f_ = __half22float2(h2sig(gf));
            uint32_t zt = h2tanh(*(uint32_t*)&gz);
            float2 z_ = __half22float2(*(__half2*)&zt);
            float2 o_ = __half22float2(h2sig(go));

            float c0 = fmaf(f_.x, cst[jr * 2],     i_.x * z_.x);
            float c1 = fmaf(f_.y, cst[jr * 2 + 1], i_.y * z_.y);
            cst[jr * 2] = c0; cst[jr * 2 + 1] = c1;
            float hv0 = o_.x * tanh_f(c0);
            float hv1 = o_.y * tanh_f(c1);

            __half2 hh = __floats2half2_rn(hv0, hv1);
            int rr = r_lo + jr * 8;
            int cc = 8 * wid + c_loc;
            *(__half2*)&h_sm[nxt][rr][cc] = hh;
            *(__half2*)&seqout[((size_t)(b0 + rr) * Tc + t) * Hc + cc] = hh;
        }
        asm volatile("cp.async.wait_group 0;");
        __syncthreads();
    }
}

// ---------------------------------------------------------------------------
// Attention scores (HMMA): s[m] = tanh(seq[m]@aw1^T + ab1)·aw2 + ab2
// ---------------------------------------------------------------------------
__global__ __launch_bounds__(256)
void attn_score_hmma(const __half* __restrict__ seq,
                     const float* __restrict__ aw1,
                     const float* __restrict__ ab1,
                     const float* __restrict__ aw2,
                     const float* __restrict__ ab2,
                     float* __restrict__ scores)
{
    extern __shared__ char smraw[];
    __half* As = (__half*)smraw;             // [128][136]
    __half* Bs = As + 128 * 136;             // [128][136] aw1 as [n][k]
    float*  abw = (float*)(Bs + 128 * 136);  // [256] = ab1 | aw2

    const int tid = threadIdx.x, wid = tid >> 5, lane = tid & 31;
    const int m0 = blockIdx.x * 128;

    {
        const uint4* Ag = (const uint4*)(seq + (size_t)m0 * Hc);
        for (int i = tid; i < 128 * 16; i += 256) {
            int r = i >> 4, ch = i & 15;
            *(uint4*)(As + r * 136 + ch * 8) = Ag[i];
        }
        const float4* Wg = (const float4*)aw1;
        for (int i = tid; i < 128 * 32; i += 256) {
            int r = i >> 5, ch = i & 31;
            float4 v = Wg[i];
            *(__half2*)(Bs + r * 136 + ch * 4)     = __floats2half2_rn(v.x, v.y);
            *(__half2*)(Bs + r * 136 + ch * 4 + 2) = __floats2half2_rn(v.z, v.w);
        }
        if (tid < 128) abw[tid] = ab1[tid];
        else if (tid < 256) abw[tid] = aw2[tid - 128];
    }
    __syncthreads();

    const int mat = lane >> 3, lr = lane & 7;
    float acc[16][4];
#pragma unroll
    for (int i = 0; i < 16; i++)
#pragma unroll
        for (int j = 0; j < 4; j++) acc[i][j] = 0.f;

#pragma unroll
    for (int kt = 0; kt < 8; kt++) {
        uint32_t a[4];
        {
            int row = wid * 16 + (mat & 1) * 8 + lr;
            int col = kt * 16 + (mat >> 1) * 8;
            ldsm4(su32(As + row * 136 + col), a[0], a[1], a[2], a[3]);
        }
#pragma unroll
        for (int nq = 0; nq < 8; nq++) {
            int nrow = nq * 16 + (mat >> 1) * 8 + lr;
            int col  = kt * 16 + (mat & 1) * 8;
            uint32_t r0, r1, r2, r3;
            ldsm4(su32(Bs + nrow * 136 + col), r0, r1, r2, r3);
            uint32_t bA[2] = {r0, r1}, bB[2] = {r2, r3};
            mma16816(acc[nq * 2], a, bA);
            mma16816(acc[nq * 2 + 1], a, bB);
        }
    }

    float s0 = 0.f, s1 = 0.f;
#pragma unroll
    for (int nt = 0; nt < 16; nt++) {
        int c = nt * 8 + 2 * (lane & 3);
        float2 bb = *(float2*)&abw[c];
        float2 ww = *(float2*)&abw[128 + c];
        s0 += tanh_f(acc[nt][0] + bb.x) * ww.x + tanh_f(acc[nt][1] + bb.y) * ww.y;
        s1 += tanh_f(acc[nt][2] + bb.x) * ww.x + tanh_f(acc[nt][3] + bb.y) * ww.y;
    }
    s0 += __shfl_xor_sync(0xffffffffu, s0, 1);
    s0 += __shfl_xor_sync(0xffffffffu, s0, 2);
    s1 += __shfl_xor_sync(0xffffffffu, s1, 1);
    s1 += __shfl_xor_sync(0xffffffffu, s1, 2);
    if ((lane & 3) == 0) {
        float bv = ab2[0];
        int r = m0 + wid * 16 + (lane >> 2);
        scores[r]     = s0 + bv;
        scores[r + 8] = s1 + bv;
    }
}

// ---------------------------------------------------------------------------
// Softmax over T + context + MLP head. One block per batch row, 128 threads.
// ---------------------------------------------------------------------------
__global__ __launch_bounds__(128)
void head_kernel(const __half* __restrict__ seq,
                 const float* __restrict__ scores,
                 const float* __restrict__ fw1, const float* __restrict__ fb1,
                 const float* __restrict__ fw2, const float* __restrict__ fb2,
                 const float* __restrict__ fw3, const float* __restrict__ fb3,
                 float* __restrict__ out)
{
    extern __shared__ float sm[];
    float* wbuf = sm;                    // [128*129]
    float* attn = wbuf + 128 * 129;      // [256]
    float* ctx  = attn + 256;            // [128]
    float* h1   = ctx + 128;             // [128]
    float* h2   = h1 + 128;              // [64]
    float* red  = h2 + 64;               // [4]

    const int b = blockIdx.x;
    const int tid = threadIdx.x;
    const int wid = tid >> 5;
    const int lid = tid & 31;

    float s0 = scores[(size_t)b * Tc + tid];
    float s1 = scores[(size_t)b * Tc + 128 + tid];
    float mx = fmaxf(s0, s1);
#pragma unroll
    for (int off = 16; off > 0; off >>= 1)
        mx = fmaxf(mx, __shfl_xor_sync(0xffffffffu, mx, off));
    if (lid == 0) red[wid] = mx;
    __syncthreads();
    float m4 = fmaxf(fmaxf(red[0], red[1]), fmaxf(red[2], red[3]));
    __syncthreads();

    float e0 = __expf(s0 - m4);
    float e1 = __expf(s1 - m4);
    float ps = e0 + e1;
#pragma unroll
    for (int off = 16; off > 0; off >>= 1)
        ps += __shfl_xor_sync(0xffffffffu, ps, off);
    if (lid == 0) red[wid] = ps;
    __syncthreads();
    float total = red[0] + red[1] + red[2] + red[3];
    float inv = __fdividef(1.0f, total);
    attn[tid]       = e0 * inv;
    attn[tid + 128] = e1 * inv;
    __syncthreads();

    {
        const __half* sp = seq + (size_t)b * Tc * Hc + tid;
        float acc = 0.f;
#pragma unroll 4
        for (int t = 0; t < Tc; t++)
            acc = fmaf(attn[t], __half2float(sp[(size_t)t * Hc]), acc);
        ctx[tid] = acc;
    }

    for (int idx = tid; idx < 128 * 128; idx += 128) {
        int j = idx >> 7, k = idx & 127;
        wbuf[j * 129 + k] = fw1[idx];
    }
    __syncthreads();
    {
        float a1 = fb1[tid];
        const float* wr = wbuf + tid * 129;
#pragma unroll 4
        for (int k = 0; k < 128; k++) a1 = fmaf(wr[k], ctx[k], a1);
        h1[tid] = fmaxf(a1, 0.f);
    }
    __syncthreads();

    for (int idx = tid; idx < 64 * 128; idx += 128) {
        int j = idx >> 7, k = idx & 127;
        wbuf[j * 129 + k] = fw2[idx];
    }
    __syncthreads();
    if (tid < 64) {
        float a2 = fb2[tid];
        const float* wr = wbuf + tid * 129;
#pragma unroll 4
        for (int k = 0; k < 128; k++) a2 = fmaf(wr[k], h1[k], a2);
        h2[tid] = fmaxf(a2, 0.f);
    }
    __syncthreads();

    float p = (tid < 64) ? fw3[tid] * h2[tid] : 0.f;
#pragma unroll
    for (int off = 16; off > 0; off >>= 1)
        p += __shfl_xor_sync(0xffffffffu, p, off);
    if (lid == 0) red[wid] = p;
    __syncthreads();
    if (tid == 0) out[b] = red[0] + red[1] + red[2] + red[3] + fb3[0];
}

// ---------------------------------------------------------------------------
// Launch
// ---------------------------------------------------------------------------
extern "C" void kernel_launch(void* const* d_in, const int* in_sizes, int n_in,
                              void* d_out, int out_size)
{
    const float* x     = (const float*)d_in[0];
    const float* w_ih0 = (const float*)d_in[1];
    const float* w_hh0 = (const float*)d_in[2];
    const float* b_ih0 = (const float*)d_in[3];
    const float* b_hh0 = (const float*)d_in[4];
    const float* w_ih1 = (const float*)d_in[5];
    const float* w_hh1 = (const float*)d_in[6];
    const float* b_ih1 = (const float*)d_in[7];
    const float* b_hh1 = (const float*)d_in[8];
    const float* aw1   = (const float*)d_in[9];
    const float* ab1   = (const float*)d_in[10];
    const float* aw2   = (const float*)d_in[11];
    const float* ab2   = (const float*)d_in[12];
    const float* fw1   = (const float*)d_in[13];
    const float* fb1   = (const float*)d_in[14];
    const float* fw2   = (const float*)d_in[15];
    const float* fb2   = (const float*)d_in[16];
    const float* fw3   = (const float*)d_in[17];
    const float* fb3   = (const float*)d_in[18];
    float* out = (float*)d_out;

    __half *pre_p, *seq0_p, *seq1_p;
    float *scores_p;
    cudaGetSymbolAddress((void**)&pre_p,    g_pre);
    cudaGetSymbolAddress((void**)&seq0_p,   g_seq0);
    cudaGetSymbolAddress((void**)&seq1_p,   g_seq1);
    cudaGetSymbolAddress((void**)&scores_p, g_scores);

    const int sm_g64  = 2 * 128 * 72 * 2 + 512;    // 37376 (staging 34816 fits in As+Bs)
    const int sm_g128 = 2 * 128 * 136 * 2 + 512;   // 70144
    const int sm_attn = 2 * 128 * 136 * 2 + 1024;  // 70656
    const int sm_head = (128 * 129 + 256 + 128 + 128 + 64 + 4) * 4;

    cudaFuncSetAttribute(gemm_pre_hmma<64, false>, cudaFuncAttributeMaxDynamicSharedMemorySize, sm_g64);
    cudaFuncSetAttribute(gemm_pre_hmma<128, true>, cudaFuncAttributeMaxDynamicSharedMemorySize, sm_g128);
    cudaFuncSetAttribute(attn_score_hmma,          cudaFuncAttributeMaxDynamicSharedMemorySize, sm_attn);
    cudaFuncSetAttribute(head_kernel,              cudaFuncAttributeMaxDynamicSharedMemorySize, sm_head);

    dim3 ggrid(Mc / 128, 4);

    // Layer 0
    gemm_pre_hmma<64, false><<<ggrid, 256, sm_g64>>>(x, w_ih0, b_ih0, b_hh0, pre_p);
    lstm_rec_hmma<<<Bc / 16, 512>>>(pre_p, w_hh0, seq0_p);

    // Layer 1
    gemm_pre_hmma<128, true><<<ggrid, 256, sm_g128>>>(seq0_p, w_ih1, b_ih1, b_hh1, pre_p);
    lstm_rec_hmma<<<Bc / 16, 512>>>(pre_p, w_hh1, seq1_p);

    // Attention scores
    attn_score_hmma<<<Mc / 128, 256, sm_attn>>>(seq1_p, aw1, ab1, aw2, ab2, scores_p);

    // Softmax + context + MLP head
    head_kernel<<<Bc, 128, sm_head>>>(seq1_p, scores_p, fw1, fb1, fw2, fb2, fw3, fb3, out);
}

// round 5
// speedup vs baseline: 1.7975x; 1.7975x over previous
#include <cuda_runtime.h>
#include <cuda_fp16.h>
#include <cstdint>

#define Bc 2048
#define Tc 256
#define Ic 64
#define Hc 128
#define Gc 512
#define Mc (Bc * Tc)

// ---------------------------------------------------------------------------
// Scratch (device globals; no allocation allowed)
// ---------------------------------------------------------------------------
__device__ __half g_xh[(size_t)Mc * Ic];         // x converted to fp16 [B][T][64]
__device__ __half g_seq0[(size_t)Mc * Hc];       // layer0 hidden [B][T][H] fp16
__device__ __half g_seq1[(size_t)Mc * Hc];       // layer1 hidden [B][T][H] fp16
__device__ float  g_scores[(size_t)Bc * Tc];     // attention logits [B][T]
__device__ uint2  g_wf0[4 * 4 * 16 * 32];        // w_ih0 frag-ordered (K=64)
__device__ uint2  g_wf1[8 * 4 * 16 * 32];        // w_ih1 frag-ordered (K=128)

// ---------------------------------------------------------------------------
// PTX helpers
// ---------------------------------------------------------------------------
__device__ __forceinline__ uint32_t su32(const void* p) {
    return (uint32_t)__cvta_generic_to_shared(p);
}
__device__ __forceinline__ void ldsm4(uint32_t a, uint32_t& r0, uint32_t& r1,
                                      uint32_t& r2, uint32_t& r3) {
    asm volatile("ldmatrix.sync.aligned.m8n8.x4.shared.b16 {%0,%1,%2,%3},[%4];"
                 : "=r"(r0), "=r"(r1), "=r"(r2), "=r"(r3) : "r"(a));
}
__device__ __forceinline__ void mma16816(float* d, const uint32_t* a, const uint32_t* b) {
    asm volatile(
        "mma.sync.aligned.m16n8k16.row.col.f32.f16.f16.f32 "
        "{%0,%1,%2,%3},{%4,%5,%6,%7},{%8,%9},{%0,%1,%2,%3};"
        : "+f"(d[0]), "+f"(d[1]), "+f"(d[2]), "+f"(d[3])
        : "r"(a[0]), "r"(a[1]), "r"(a[2]), "r"(a[3]), "r"(b[0]), "r"(b[1]));
}
__device__ __forceinline__ float tanh_f(float x) {
    float y; asm("tanh.approx.f32 %0,%1;" : "=f"(y) : "f"(x)); return y;
}
__device__ __forceinline__ float sig_f(float x) {
    return fmaf(tanh_f(0.5f * x), 0.5f, 0.5f);
}
__device__ __forceinline__ void cpa16(uint32_t d, const void* s) {
    asm volatile("cp.async.cg.shared.global [%0],[%1],16;" :: "r"(d), "l"(s));
}

// ---------------------------------------------------------------------------
// x fp32 -> fp16
// ---------------------------------------------------------------------------
__global__ __launch_bounds__(256)
void xconvert(const float* __restrict__ x, __half* __restrict__ xh)
{
    size_t i = ((size_t)blockIdx.x * 256 + threadIdx.x) * 4;
    float4 v = *(const float4*)(x + i);
    __half2 h0 = __floats2half2_rn(v.x, v.y);
    __half2 h1 = __floats2half2_rn(v.z, v.w);
    *(uint2*)(xh + i) = make_uint2(*(uint32_t*)&h0, *(uint32_t*)&h1);
}

// ---------------------------------------------------------------------------
// Fragment-order weight prep:  W[512][K] fp32 -> [kt][g][warp][lane]{2xu32}
// B-frag mapping for mma.m16n8k16 (B = [n][k] row-major):
//   n = 128*g + 8*warp + (lane>>2);  reg0: k = kt*16 + 2*(lane&3) + {0,1}
//                                    reg1: k = kt*16 + 8 + 2*(lane&3) + {0,1}
// ---------------------------------------------------------------------------
template <int KT>
__global__ __launch_bounds__(256)
void fragprep(const float* __restrict__ W, uint2* __restrict__ out)
{
    int idx = blockIdx.x * 256 + threadIdx.x;
    if (idx >= KT * 4 * 16 * 32) return;
    int lane = idx & 31;
    int rest = idx >> 5;
    int w  = rest & 15; rest >>= 4;
    int g  = rest & 3;
    int kt = rest >> 2;
    int n  = 128 * g + 8 * w + (lane >> 2);
    int k0 = kt * 16 + 2 * (lane & 3);
    const float* row = W + (size_t)n * (KT * 16);
    __half2 v0 = __floats2half2_rn(row[k0],     row[k0 + 1]);
    __half2 v1 = __floats2half2_rn(row[k0 + 8], row[k0 + 9]);
    out[idx] = make_uint2(*(uint32_t*)&v0, *(uint32_t*)&v1);
}

// ---------------------------------------------------------------------------
// Fused LSTM layer: input projection + recurrence in one kernel.
// Block = 16 batch rows, 16 warps. Per 2-step window:
//   Phase A: P[t],P[t+1] = in[t..t+1] @ w_ih^T  (no serial dep; fills bubbles)
//   Phase B: 2 serial steps of h@w_hh + cell (w_hh frags in registers).
// ---------------------------------------------------------------------------
template <int KT_IH>   // 4 -> K=64 (layer0), 8 -> K=128 (layer1)
__global__ __launch_bounds__(512, 1)
void lstm_fused(const __half* __restrict__ in,     // [B][T][K]
                const uint2* __restrict__ wfrag,   // [KT_IH][4][16][32]
                const float* __restrict__ w_hh,    // [512][128]
                const float* __restrict__ b_ih,
                const float* __restrict__ b_hh,
                __half* __restrict__ seqout)       // [B][T][128]
{
    constexpr int K  = KT_IH * 16;
    constexpr int KP = K + 8;
    constexpr int CH = K / 8;           // 16B chunks per row
    constexpr int WF = KT_IH * 4 * 16 * 32;

    extern __shared__ char smr[];
    uint2*  wf_sm = (uint2*)smr;                        // [WF]
    __half* h_sm  = (__half*)(wf_sm + WF);              // [2][16][136]
    __half* sbuf  = h_sm + 2 * 16 * 136;                // [2][2][16][KP]
    float*  bias  = (float*)(sbuf + 2 * 2 * 16 * KP);   // [512]

    const int tid = threadIdx.x, wid = tid >> 5, lane = tid & 31;
    const int b0 = blockIdx.x * 16;
    const int mat = lane >> 3, lr = lane & 7;
    const int r_lo = lane >> 2, c_loc = 2 * (lane & 3);

    // stage frag-ordered w_ih into SMEM
    for (int i = tid; i < WF / 2; i += 512)
        ((uint4*)wf_sm)[i] = ((const uint4*)wfrag)[i];
    if (tid < 512) bias[tid] = b_ih[tid] + b_hh[tid];

    // persistent w_hh B-fragments (warp w owns cols n = 128g + 8w + n_off)
    uint32_t bf[8][4][2];
#pragma unroll
    for (int g = 0; g < 4; g++) {
        int n = 128 * g + 8 * wid + r_lo;
        const float* wr = w_hh + (size_t)n * Hc + c_loc;
#pragma unroll
        for (int kt = 0; kt < 8; kt++) {
            float2 v0 = *(const float2*)(wr + kt * 16);
            float2 v1 = *(const float2*)(wr + kt * 16 + 8);
            __half2 h0 = __floats2half2_rn(v0.x, v0.y);
            __half2 h1 = __floats2half2_rn(v1.x, v1.y);
            bf[kt][g][0] = *(uint32_t*)&h0;
            bf[kt][g][1] = *(uint32_t*)&h1;
        }
    }

    for (int i = tid; i < 2 * 16 * 136; i += 512)
        h_sm[i] = __float2half(0.f);

    // prefetch window 0 (t=0,1) into sbuf[0]
    for (int i = tid; i < 2 * 16 * CH; i += 512) {
        int slab = i / (16 * CH), rem = i % (16 * CH);
        int r = rem / CH, ch = rem % CH;
        cpa16(su32(&sbuf[((0 * 2 + slab) * 16 + r) * KP + ch * 8]),
              in + ((size_t)(b0 + r) * Tc + slab) * K + ch * 8);
    }
    asm volatile("cp.async.commit_group;");

    float cst[4];
#pragma unroll
    for (int j = 0; j < 4; j++) cst[j] = 0.f;

    int ph = 0;

    for (int w = 0; w < Tc / 2; w++) {
        const int cur = w & 1;
        asm volatile("cp.async.wait_group 0;");
        __syncthreads();

        // ---------------- Phase A: input projection for t0, t0+1 ----------
        float accA[4][4], accB[4][4];
#pragma unroll
        for (int g = 0; g < 4; g++)
#pragma unroll
            for (int j = 0; j < 4; j++) { accA[g][j] = 0.f; accB[g][j] = 0.f; }

#pragma unroll
        for (int kt = 0; kt < KT_IH; kt++) {
            uint32_t a0[4], a1[4];
            int row = (mat & 1) * 8 + lr;
            int col = kt * 16 + (mat >> 1) * 8;
            ldsm4(su32(&sbuf[((cur * 2 + 0) * 16 + row) * KP + col]),
                  a0[0], a0[1], a0[2], a0[3]);
            ldsm4(su32(&sbuf[((cur * 2 + 1) * 16 + row) * KP + col]),
                  a1[0], a1[1], a1[2], a1[3]);
#pragma unroll
            for (int g = 0; g < 4; g++) {
                uint2 wv = wf_sm[((kt * 4 + g) * 16 + wid) * 32 + lane];
                mma16816(accA[g], a0, (uint32_t*)&wv);
                mma16816(accB[g], a1, (uint32_t*)&wv);
            }
        }

        // add biases once per window
#pragma unroll
        for (int g = 0; g < 4; g++) {
            float2 bv = *(const float2*)&bias[128 * g + 8 * wid + c_loc];
#pragma unroll
            for (int j = 0; j < 4; j++) {
                float b = (j & 1) ? bv.y : bv.x;
                accA[g][j] += b; accB[g][j] += b;
            }
        }

        // prefetch next window (overlaps phase B)
        if (w + 1 < Tc / 2) {
            for (int i = tid; i < 2 * 16 * CH; i += 512) {
                int slab = i / (16 * CH), rem = i % (16 * CH);
                int r = rem / CH, ch = rem % CH;
                cpa16(su32(&sbuf[(((cur ^ 1) * 2 + slab) * 16 + r) * KP + ch * 8]),
                      in + ((size_t)(b0 + r) * Tc + (2 * (w + 1) + slab)) * K + ch * 8);
            }
        }
        asm volatile("cp.async.commit_group;");

        // ---------------- Phase B: two serial recurrence steps -------------
#pragma unroll
        for (int s = 0; s < 2; s++) {
            float (*acc)[4] = (s == 0) ? accA : accB;
            const int t = 2 * w + s;
            __syncthreads();

#pragma unroll
            for (int kt = 0; kt < 8; kt++) {
                uint32_t a[4];
                a[0] = *(const uint32_t*)&h_sm[(ph * 16 + r_lo    ) * 136 + kt * 16 + c_loc];
                a[1] = *(const uint32_t*)&h_sm[(ph * 16 + r_lo + 8) * 136 + kt * 16 + c_loc];
                a[2] = *(const uint32_t*)&h_sm[(ph * 16 + r_lo    ) * 136 + kt * 16 + c_loc + 8];
                a[3] = *(const uint32_t*)&h_sm[(ph * 16 + r_lo + 8) * 136 + kt * 16 + c_loc + 8];
#pragma unroll
                for (int g = 0; g < 4; g++) mma16816(acc[g], a, bf[kt][g]);
            }

            // fp32 cell
#pragma unroll
            for (int jr = 0; jr < 2; jr++) {
                float hv0, hv1;
#pragma unroll
                for (int jc = 0; jc < 2; jc++) {
                    int j = jr * 2 + jc;
                    float i_ = sig_f(acc[0][j]);
                    float f_ = sig_f(acc[1][j]);
                    float z_ = tanh_f(acc[2][j]);
                    float o_ = sig_f(acc[3][j]);
                    float cn = fmaf(f_, cst[j], i_ * z_);
                    cst[j] = cn;
                    float hv = o_ * tanh_f(cn);
                    if (jc == 0) hv0 = hv; else hv1 = hv;
                }
                __half2 hh = __floats2half2_rn(hv0, hv1);
                int rr = r_lo + jr * 8;
                int cc = 8 * wid + c_loc;
                *(__half2*)&h_sm[((ph ^ 1) * 16 + rr) * 136 + cc] = hh;
                *(__half2*)&seqout[((size_t)(b0 + rr) * Tc + t) * Hc + cc] = hh;
            }
            ph ^= 1;
        }
    }
}

// ---------------------------------------------------------------------------
// Attention scores (HMMA): s[m] = tanh(seq[m]@aw1^T + ab1)·aw2 + ab2
// ---------------------------------------------------------------------------
__global__ __launch_bounds__(256)
void attn_score_hmma(const __half* __restrict__ seq,
                     const float* __restrict__ aw1,
                     const float* __restrict__ ab1,
                     const float* __restrict__ aw2,
                     const float* __restrict__ ab2,
                     float* __restrict__ scores)
{
    extern __shared__ char smraw[];
    __half* As = (__half*)smraw;             // [128][136]
    __half* Bs = As + 128 * 136;             // [128][136] aw1 as [n][k]
    float*  abw = (float*)(Bs + 128 * 136);  // [256] = ab1 | aw2

    const int tid = threadIdx.x, wid = tid >> 5, lane = tid & 31;
    const int m0 = blockIdx.x * 128;

    {
        const uint4* Ag = (const uint4*)(seq + (size_t)m0 * Hc);
        for (int i = tid; i < 128 * 16; i += 256) {
            int r = i >> 4, ch = i & 15;
            *(uint4*)(As + r * 136 + ch * 8) = Ag[i];
        }
        const float4* Wg = (const float4*)aw1;
        for (int i = tid; i < 128 * 32; i += 256) {
            int r = i >> 5, ch = i & 31;
            float4 v = Wg[i];
            *(__half2*)(Bs + r * 136 + ch * 4)     = __floats2half2_rn(v.x, v.y);
            *(__half2*)(Bs + r * 136 + ch * 4 + 2) = __floats2half2_rn(v.z, v.w);
        }
        if (tid < 128) abw[tid] = ab1[tid];
        else if (tid < 256) abw[tid] = aw2[tid - 128];
    }
    __syncthreads();

    const int mat = lane >> 3, lr = lane & 7;
    float acc[16][4];
#pragma unroll
    for (int i = 0; i < 16; i++)
#pragma unroll
        for (int j = 0; j < 4; j++) acc[i][j] = 0.f;

#pragma unroll
    for (int kt = 0; kt < 8; kt++) {
        uint32_t a[4];
        {
            int row = wid * 16 + (mat & 1) * 8 + lr;
            int col = kt * 16 + (mat >> 1) * 8;
            ldsm4(su32(As + row * 136 + col), a[0], a[1], a[2], a[3]);
        }
#pragma unroll
        for (int nq = 0; nq < 8; nq++) {
            int nrow = nq * 16 + (mat >> 1) * 8 + lr;
            int col  = kt * 16 + (mat & 1) * 8;
            uint32_t r0, r1, r2, r3;
            ldsm4(su32(Bs + nrow * 136 + col), r0, r1, r2, r3);
            uint32_t bA[2] = {r0, r1}, bB[2] = {r2, r3};
            mma16816(acc[nq * 2], a, bA);
            mma16816(acc[nq * 2 + 1], a, bB);
        }
    }

    float s0 = 0.f, s1 = 0.f;
#pragma unroll
    for (int nt = 0; nt < 16; nt++) {
        int c = nt * 8 + 2 * (lane & 3);
        float2 bb = *(float2*)&abw[c];
        float2 ww = *(float2*)&abw[128 + c];
        s0 += tanh_f(acc[nt][0] + bb.x) * ww.x + tanh_f(acc[nt][1] + bb.y) * ww.y;
        s1 += tanh_f(acc[nt][2] + bb.x) * ww.x + tanh_f(acc[nt][3] + bb.y) * ww.y;
    }
    s0 += __shfl_xor_sync(0xffffffffu, s0, 1);
    s0 += __shfl_xor_sync(0xffffffffu, s0, 2);
    s1 += __shfl_xor_sync(0xffffffffu, s1, 1);
    s1 += __shfl_xor_sync(0xffffffffu, s1, 2);
    if ((lane & 3) == 0) {
        float bv = ab2[0];
        int r = m0 + wid * 16 + (lane >> 2);
        scores[r]     = s0 + bv;
        scores[r + 8] = s1 + bv;
    }
}

// ---------------------------------------------------------------------------
// Softmax over T + context + MLP head. One block per batch row, 128 threads.
// ---------------------------------------------------------------------------
__global__ __launch_bounds__(128)
void head_kernel(const __half* __restrict__ seq,
                 const float* __restrict__ scores,
                 const float* __restrict__ fw1, const float* __restrict__ fb1,
                 const float* __restrict__ fw2, const float* __restrict__ fb2,
                 const float* __restrict__ fw3, const float* __restrict__ fb3,
                 float* __restrict__ out)
{
    extern __shared__ float sm[];
    float* wbuf = sm;                    // [128*129]
    float* attn = wbuf + 128 * 129;      // [256]
    float* ctx  = attn + 256;            // [128]
    float* h1   = ctx + 128;             // [128]
    float* h2   = h1 + 128;              // [64]
    float* red  = h2 + 64;               // [4]

    const int b = blockIdx.x;
    const int tid = threadIdx.x;
    const int wid = tid >> 5;
    const int lid = tid & 31;

    float s0 = scores[(size_t)b * Tc + tid];
    float s1 = scores[(size_t)b * Tc + 128 + tid];
    float mx = fmaxf(s0, s1);
#pragma unroll
    for (int off = 16; off > 0; off >>= 1)
        mx = fmaxf(mx, __shfl_xor_sync(0xffffffffu, mx, off));
    if (lid == 0) red[wid] = mx;
    __syncthreads();
    float m4 = fmaxf(fmaxf(red[0], red[1]), fmaxf(red[2], red[3]));
    __syncthreads();

    float e0 = __expf(s0 - m4);
    float e1 = __expf(s1 - m4);
    float ps = e0 + e1;
#pragma unroll
    for (int off = 16; off > 0; off >>= 1)
        ps += __shfl_xor_sync(0xffffffffu, ps, off);
    if (lid == 0) red[wid] = ps;
    __syncthreads();
    float total = red[0] + red[1] + red[2] + red[3];
    float inv = __fdividef(1.0f, total);
    attn[tid]       = e0 * inv;
    attn[tid + 128] = e1 * inv;
    __syncthreads();

    {
        const __half* sp = seq + (size_t)b * Tc * Hc + tid;
        float acc = 0.f;
#pragma unroll 4
        for (int t = 0; t < Tc; t++)
            acc = fmaf(attn[t], __half2float(sp[(size_t)t * Hc]), acc);
        ctx[tid] = acc;
    }

    for (int idx = tid; idx < 128 * 128; idx += 128) {
        int j = idx >> 7, k = idx & 127;
        wbuf[j * 129 + k] = fw1[idx];
    }
    __syncthreads();
    {
        float a1 = fb1[tid];
        const float* wr = wbuf + tid * 129;
#pragma unroll 4
        for (int k = 0; k < 128; k++) a1 = fmaf(wr[k], ctx[k], a1);
        h1[tid] = fmaxf(a1, 0.f);
    }
    __syncthreads();

    for (int idx = tid; idx < 64 * 128; idx += 128) {
        int j = idx >> 7, k = idx & 127;
        wbuf[j * 129 + k] = fw2[idx];
    }
    __syncthreads();
    if (tid < 64) {
        float a2 = fb2[tid];
        const float* wr = wbuf + tid * 129;
#pragma unroll 4
        for (int k = 0; k < 128; k++) a2 = fmaf(wr[k], h1[k], a2);
        h2[tid] = fmaxf(a2, 0.f);
    }
    __syncthreads();

    float p = (tid < 64) ? fw3[tid] * h2[tid] : 0.f;
#pragma unroll
    for (int off = 16; off > 0; off >>= 1)
        p += __shfl_xor_sync(0xffffffffu, p, off);
    if (lid == 0) red[wid] = p;
    __syncthreads();
    if (tid == 0) out[b] = red[0] + red[1] + red[2] + red[3] + fb3[0];
}

// ---------------------------------------------------------------------------
// Launch
// ---------------------------------------------------------------------------
extern "C" void kernel_launch(void* const* d_in, const int* in_sizes, int n_in,
                              void* d_out, int out_size)
{
    const float* x     = (const float*)d_in[0];
    const float* w_ih0 = (const float*)d_in[1];
    const float* w_hh0 = (const float*)d_in[2];
    const float* b_ih0 = (const float*)d_in[3];
    const float* b_hh0 = (const float*)d_in[4];
    const float* w_ih1 = (const float*)d_in[5];
    const float* w_hh1 = (const float*)d_in[6];
    const float* b_ih1 = (const float*)d_in[7];
    const float* b_hh1 = (const float*)d_in[8];
    const float* aw1   = (const float*)d_in[9];
    const float* ab1   = (const float*)d_in[10];
    const float* aw2   = (const float*)d_in[11];
    const float* ab2   = (const float*)d_in[12];
    const float* fw1   = (const float*)d_in[13];
    const float* fb1   = (const float*)d_in[14];
    const float* fw2   = (const float*)d_in[15];
    const float* fb2   = (const float*)d_in[16];
    const float* fw3   = (const float*)d_in[17];
    const float* fb3   = (const float*)d_in[18];
    float* out = (float*)d_out;

    __half *xh_p, *seq0_p, *seq1_p;
    float *scores_p;
    uint2 *wf0_p, *wf1_p;
    cudaGetSymbolAddress((void**)&xh_p,     g_xh);
    cudaGetSymbolAddress((void**)&seq0_p,   g_seq0);
    cudaGetSymbolAddress((void**)&seq1_p,   g_seq1);
    cudaGetSymbolAddress((void**)&scores_p, g_scores);
    cudaGetSymbolAddress((void**)&wf0_p,    g_wf0);
    cudaGetSymbolAddress((void**)&wf1_p,    g_wf1);

    const int sm_f0 = 4 * 4 * 16 * 32 * 8 + 2 * 16 * 136 * 2 + 2 * 2 * 16 * 72 * 2 + 2048;
    const int sm_f1 = 8 * 4 * 16 * 32 * 8 + 2 * 16 * 136 * 2 + 2 * 2 * 16 * 136 * 2 + 2048;
    const int sm_attn = 2 * 128 * 136 * 2 + 1024;
    const int sm_head = (128 * 129 + 256 + 128 + 128 + 64 + 4) * 4;

    cudaFuncSetAttribute(lstm_fused<4>,   cudaFuncAttributeMaxDynamicSharedMemorySize, sm_f0);
    cudaFuncSetAttribute(lstm_fused<8>,   cudaFuncAttributeMaxDynamicSharedMemorySize, sm_f1);
    cudaFuncSetAttribute(attn_score_hmma, cudaFuncAttributeMaxDynamicSharedMemorySize, sm_attn);
    cudaFuncSetAttribute(head_kernel,     cudaFuncAttributeMaxDynamicSharedMemorySize, sm_head);

    // prep: x -> fp16, w_ih -> fragment order
    xconvert<<<Mc * Ic / 4 / 256, 256>>>(x, xh_p);
    fragprep<4><<<(4 * 4 * 16 * 32) / 256, 256>>>(w_ih0, wf0_p);
    fragprep<8><<<(8 * 4 * 16 * 32) / 256, 256>>>(w_ih1, wf1_p);

    // fused LSTM layers (input projection + recurrence)
    lstm_fused<4><<<Bc / 16, 512, sm_f0>>>(xh_p, wf0_p, w_hh0, b_ih0, b_hh0, seq0_p);
    lstm_fused<8><<<Bc / 16, 512, sm_f1>>>(seq0_p, wf1_p, w_hh1, b_ih1, b_hh1, seq1_p);

    // attention + head
    attn_score_hmma<<<Mc / 128, 256, sm_attn>>>(seq1_p, aw1, ab1, aw2, ab2, scores_p);
    head_kernel<<<Bc, 128, sm_head>>>(seq1_p, scores_p, fw1, fb1, fw2, fb2, fw3, fb3, out);
}